// round 9
// baseline (speedup 1.0000x reference)
#include <cuda_runtime.h>
#include <cuda_bf16.h>
#include <cstdint>

#define Bsz 2
#define Ssz 4096
#define Hsz 16
#define DK  128
#define CC  64
#define NCH (Ssz/CC)      // 64 chunks
#define BH  (Bsz*Hsz)     // 32
#define CCP 68            // phase1 transposed row pad
#define SPLIT 4
#define DVS (DK/SPLIT)    // 32
#define ATP 68            // phase2 attnT row pad
#define VNP 36            // phase2 DVS-wide row pad
#define REDW 20           // reduction row stride (th*20 mod 32 distinct per 8 lanes)

// -------- scratch (device globals: allocation-free rule) --------
__device__ float g_qg[(size_t)BH*Ssz*DK];   // normalized q * Dk^-0.5 * exp(gcs)
__device__ float g_kn[(size_t)BH*Ssz*DK];   // normalized k
__device__ float g_u [(size_t)BH*Ssz*DK];   // Tinv @ (v*beta)
__device__ float g_w [(size_t)BH*Ssz*DK];   // Tinv @ (k*beta*exp(gcs))  (kcd)
__device__ float g_at[(size_t)BH*Ssz*CC];   // intra-chunk attn TRANSPOSED: [j][i]
__device__ float g_gc[(size_t)BH*Ssz];      // within-chunk cumsum of g

// 16B async copy global->shared
__device__ __forceinline__ void cpa16(void* dst, const void* src) {
  unsigned d = (unsigned)__cvta_generic_to_shared(dst);
  asm volatile("cp.async.cg.shared.global [%0], [%1], 16;" :: "r"(d), "l"(src));
}
__device__ __forceinline__ void cpa_commit() {
  asm volatile("cp.async.commit_group;");
}
template<int N> __device__ __forceinline__ void cpa_wait() {
  asm volatile("cp.async.wait_group %0;" :: "n"(N) : "memory");
}

// swizzled float offset for kc/qg tiles (row stride 128, rotate c4 by row>>2)
__device__ __forceinline__ int swzo(int r, int c4) {
  return (r << 7) + (((c4 + (r >> 2)) & 31) << 2);
}

struct P1S {
  float knT[DK][CCP];
  float qgT[DK][CCP];
  float A  [CC][CC];
  float gcs[CC];
  float bet[CC];
  float eg[CC];
  float er[CC];
  float ebg[CC];
};

struct P2S {
  float st [DK][VNP];      // state slice [DK][DVS]
  float kn [CC*DK];        // unswizzled, stride 128
  float kc [2][CC*DK];     // double-buffered, swizzled
  float qg [CC*DK];        // swizzled
  float uu [CC][VNP];
  float atT[CC][ATP];      // attn transposed [j][i]
  float vn [CC][VNP];
  float vnw[CC][VNP];      // vn * exp(g_last - gcs_i)
  float red[3][128][REDW]; // split-K partials (quarters 1..3)
  float w  [CC];
  float elv;               // exp(g_last)
};

// ================= Phase 1: per-chunk precompute (grid = BH*NCH) =================
__global__ void __launch_bounds__(256, 2) phase1_kernel(
    const float* __restrict__ q, const float* __restrict__ k,
    const float* __restrict__ v, const float* __restrict__ g,
    const float* __restrict__ beta)
{
  extern __shared__ char smraw[];
  P1S& s = *reinterpret_cast<P1S*>(smraw);
  const int t    = threadIdx.x;
  const int lane = t & 31;
  const int warp = t >> 5;
  const int cid = blockIdx.x;
  const int bh = cid / NCH, n = cid % NCH;
  const int b = bh / Hsz, h = bh % Hsz;
  const int s0 = n * CC;

  if (t < CC) {
    s.bet[t] = beta[(size_t)(b*Ssz + s0 + t)*Hsz + h];
    s.gcs[t] = g   [(size_t)(b*Ssz + s0 + t)*Hsz + h];
  }
  __syncthreads();
  if (t < CC) {
    float x = s.gcs[t];
    #pragma unroll
    for (int o = 1; o < 32; o <<= 1) {
      float y = __shfl_up_sync(0xffffffffu, x, o);
      if (lane >= o) x += y;
    }
    s.gcs[t] = x;
  }
  __syncthreads();
  if (t < CC) {
    float gi = s.gcs[t];
    if (t >= 32) { gi += s.gcs[31]; s.gcs[t] = gi; }
    const float e = __expf(gi);
    s.eg[t]  = e;
    s.er[t]  = __expf(-gi);
    s.ebg[t] = s.bet[t] * e;
    g_gc[(size_t)bh*Ssz + s0 + t] = gi;
  }
  __syncthreads();

  for (int r = warp; r < CC; r += 8) {
    const size_t base = ((size_t)(b*Ssz + s0 + r)*Hsz + h)*DK;
    float kv[4], qv[4];
    float ssk = 0.f, ssq = 0.f;
    #pragma unroll
    for (int i = 0; i < 4; i++) {
      kv[i] = k[base + lane + 32*i]; ssk = fmaf(kv[i], kv[i], ssk);
      qv[i] = q[base + lane + 32*i]; ssq = fmaf(qv[i], qv[i], ssq);
    }
    #pragma unroll
    for (int o = 16; o; o >>= 1) {
      ssk += __shfl_xor_sync(0xffffffffu, ssk, o);
      ssq += __shfl_xor_sync(0xffffffffu, ssq, o);
    }
    const float rk = rsqrtf(ssk + 1e-6f);
    const float rq = rsqrtf(ssq + 1e-6f) * 0.08838834764831845f * s.eg[r];
    const size_t ob = ((size_t)bh*Ssz + s0 + r)*DK;
    #pragma unroll
    for (int i = 0; i < 4; i++) {
      const int d = lane + 32*i;
      const float kk = kv[i]*rk, qq = qv[i]*rq;
      s.knT[d][r] = kk; g_kn[ob + d] = kk;
      s.qgT[d][r] = qq; g_qg[ob + d] = qq;
    }
  }
  __syncthreads();

  // ---- GEMM: A (strict lower) + attn (tril) stored TRANSPOSED ----
  {
    const int ti = t >> 4, tj = t & 15;
    const size_t atb = ((size_t)bh*Ssz + s0)*CC;
    if (tj <= ti) {
      float accA[4][4] = {}, accT[4][4] = {};
      #pragma unroll 4
      for (int d = 0; d < DK; d++) {
        const float4 kd4 = *reinterpret_cast<const float4*>(&s.knT[d][ti*4]);
        const float4 qd4 = *reinterpret_cast<const float4*>(&s.qgT[d][ti*4]);
        const float4 kj4 = *reinterpret_cast<const float4*>(&s.knT[d][tj*4]);
        const float kd[4] = {kd4.x, kd4.y, kd4.z, kd4.w};
        const float qd[4] = {qd4.x, qd4.y, qd4.z, qd4.w};
        const float kj[4] = {kj4.x, kj4.y, kj4.z, kj4.w};
        #pragma unroll
        for (int a = 0; a < 4; a++)
          #pragma unroll
          for (int c = 0; c < 4; c++) {
            accA[a][c] = fmaf(kd[a], kj[c], accA[a][c]);
            accT[a][c] = fmaf(qd[a], kj[c], accT[a][c]);
          }
      }
      const float erj[4] = {s.er[tj*4], s.er[tj*4+1], s.er[tj*4+2], s.er[tj*4+3]};
      #pragma unroll
      for (int a = 0; a < 4; a++) {
        const int i = ti*4 + a;
        const float bei = s.bet[i] * s.eg[i];
        float4 av; float* ap = &av.x;
        #pragma unroll
        for (int c = 0; c < 4; c++) {
          const int j = tj*4 + c;
          ap[c] = (j < i) ? accA[a][c]*bei*erj[c] : 0.f;
        }
        *reinterpret_cast<float4*>(&s.A[i][tj*4]) = av;
      }
      #pragma unroll
      for (int c = 0; c < 4; c++) {
        const int j = tj*4 + c;
        float4 tv; float* tp = &tv.x;
        #pragma unroll
        for (int a = 0; a < 4; a++) {
          const int i = ti*4 + a;
          tp[a] = (j <= i) ? accT[a][c]*erj[c] : 0.f;
        }
        *reinterpret_cast<float4*>(&g_at[atb + (size_t)j*CC + ti*4]) = tv;
      }
    } else {
      const float4 z = {0.f, 0.f, 0.f, 0.f};
      #pragma unroll
      for (int a = 0; a < 4; a++)
        *reinterpret_cast<float4*>(&s.A[ti*4 + a][tj*4]) = z;
      #pragma unroll
      for (int c = 0; c < 4; c++)
        *reinterpret_cast<float4*>(&g_at[atb + (size_t)(tj*4 + c)*CC + ti*4]) = z;
    }
  }
  __syncthreads();

  float xr[CC];
  if (t < DK) {
    #pragma unroll 8
    for (int i = 0; i < CC; i++)
      xr[i] = v[((size_t)(b*Ssz + s0 + i)*Hsz + h)*DK + t] * s.bet[i];
  } else {
    const int d = t - DK;
    #pragma unroll 8
    for (int i = 0; i < CC; i++)
      xr[i] = s.knT[d][i] * s.ebg[i];
  }

  #pragma unroll
  for (int i = 1; i < CC; i++) {
    const float4* Ai = reinterpret_cast<const float4*>(&s.A[i][0]);
    float a0 = 0.f, a1 = 0.f, a2 = 0.f, a3 = 0.f;
    const int nq = (i + 3) >> 2;
    #pragma unroll
    for (int j4 = 0; j4 < nq; j4++) {
      const float4 av = Ai[j4];
      a0 = fmaf(av.x, xr[j4*4+0], a0);
      a1 = fmaf(av.y, xr[j4*4+1], a1);
      a2 = fmaf(av.z, xr[j4*4+2], a2);
      a3 = fmaf(av.w, xr[j4*4+3], a3);
    }
    xr[i] -= (a0 + a1) + (a2 + a3);
  }

  {
    const size_t ob = ((size_t)bh*Ssz + s0)*DK;
    if (t < DK) {
      #pragma unroll 8
      for (int i = 0; i < CC; i++) g_u[ob + (size_t)i*DK + t] = xr[i];
    } else {
      const int d = t - DK;
      #pragma unroll 8
      for (int i = 0; i < CC; i++) g_w[ob + (size_t)i*DK + d] = xr[i];
    }
  }
}

// ===== Phase 2: scan (BH*SPLIT CTAs, 512 thr, pipelined cp.async groups) =====
__global__ void __launch_bounds__(512, 1) phase2_kernel(float* __restrict__ out)
{
  extern __shared__ char smraw[];
  P2S& s = *reinterpret_cast<P2S*>(smraw);
  const int t  = threadIdx.x;
  const int bh = blockIdx.x / SPLIT;
  const int sp = blockIdx.x % SPLIT;
  const int b = bh / Hsz, h = bh % Hsz;
  const int v0 = sp * DVS;

  for (int i = t; i < DK*VNP; i += 512) (&s.st[0][0])[i] = 0.f;

  const int kh = t >> 7;        // d-quarter / split phase (0..3)
  const int th = t & 127;
  const int rg = th >> 3;       // 16 row groups (stages B/C)
  const int cg = th & 7;        // 8 col groups
  const int r0 = rg * 4;
  const int vv = cg * 4;
  const int d0D = (t >> 3) * 2; // stage D: 64 d-groups x 2 rows
  const int vvD = (t & 7) * 4;

  const size_t cb = (size_t)bh*Ssz;

  // ---- prologue: chunk-0 tiles (two groups, matching steady-state G1/G2) ----
  {
    const float* gq = g_qg + cb*DK;
    #pragma unroll
    for (int rep = 0; rep < 4; rep++) {
      const int idx = t + rep*512;
      cpa16(&s.qg[swzo(idx >> 5, idx & 31)], gq + idx*4);
    }
    { const int rr = t >> 3, c4 = (t & 7)*4;
      cpa16(&s.uu[rr][c4], g_u + (cb + rr)*DK + v0 + c4); }
    cpa_commit();                                   // ~G1(0)
    #pragma unroll
    for (int rep = 0; rep < 2; rep++) {
      const int idx = t + rep*512;
      cpa16(&s.atT[idx >> 4][(idx & 15)*4], g_at + cb*CC + idx*4);
    }
    { const float* gw = g_w + cb*DK;
      #pragma unroll
      for (int rep = 0; rep < 4; rep++) {
        const int idx = t + rep*512;
        cpa16(&s.kc[0][swzo(idx >> 5, idx & 31)], gw + idx*4);
      } }
    cpa_commit();                                   // ~G2(0) + kc[0]
  }

  for (int n = 0; n < NCH; n++) {
    const size_t rb = cb + n*CC;
    __syncthreads();  // (1) prev-chunk compute done (st, kn reads, kc buf free)

    // ---- G_top(n): kn[n] + kc[n+1] -> buf[(n+1)&1] ----
    {
      const float* gk = g_kn + rb*DK;
      #pragma unroll
      for (int rep = 0; rep < 4; rep++) {
        const int idx = t + rep*512;
        cpa16(&s.kn[idx*4], gk + idx*4);
      }
      if (n + 1 < NCH) {
        const float* gw = g_w + (rb + CC)*DK;
        float* kcn = s.kc[(n+1)&1];
        #pragma unroll
        for (int rep = 0; rep < 4; rep++) {
          const int idx = t + rep*512;
          cpa16(&kcn[swzo(idx >> 5, idx & 31)], gw + idx*4);
        }
      }
      cpa_commit();
    }
    cpa_wait<1>();    // qg[n], uu[n], atT[n], kc[n] landed (G_top may pend)
    __syncthreads();  // (2) cross-thread visibility
    if (t < CC) {
      const float gl = g_gc[rb + CC - 1];
      s.w[t] = __expf(gl - g_gc[rb + t]);
      if (t == CC-1) s.elv = __expf(gl);
    }

    // ---- stage B: va = -kc@st ; oa = qg@st  (quarter kh: 32 d's) ----
    float va[4][4] = {}, oa[4][4] = {};
    {
      const float* kcb = s.kc[n&1];
      #pragma unroll 2
      for (int d4 = 0; d4 < 8; d4++) {
        const int c4b = kh*8 + d4;
        const int d = c4b*4;
        float stc[4][4];
        #pragma unroll
        for (int m = 0; m < 4; m++) {
          const float4 s4 = *reinterpret_cast<const float4*>(&s.st[d+m][vv]);
          stc[m][0]=s4.x; stc[m][1]=s4.y; stc[m][2]=s4.z; stc[m][3]=s4.w;
        }
        #pragma unroll
        for (int a = 0; a < 4; a++) {
          const int ofs = ((r0+a) << 7) + (((c4b + rg) & 31) << 2);
          const float4 kc4 = *reinterpret_cast<const float4*>(&kcb[ofs]);
          const float4 qg4 = *reinterpret_cast<const float4*>(&s.qg[ofs]);
          const float kcm[4] = {kc4.x, kc4.y, kc4.z, kc4.w};
          const float qgm[4] = {qg4.x, qg4.y, qg4.z, qg4.w};
          #pragma unroll
          for (int m = 0; m < 4; m++)
            #pragma unroll
            for (int c = 0; c < 4; c++) {
              va[a][c] = fmaf(-kcm[m], stc[m][c], va[a][c]);
              oa[a][c] = fmaf( qgm[m], stc[m][c], oa[a][c]);
            }
        }
      }
    }
    if (kh) {
      #pragma unroll
      for (int a = 0; a < 4; a++)
        *reinterpret_cast<float4*>(&s.red[kh-1][th][a*4]) =
          make_float4(va[a][0], va[a][1], va[a][2], va[a][3]);
    }
    __syncthreads();  // (3)
    if (!kh) {
      #pragma unroll
      for (int a = 0; a < 4; a++) {
        const int i = r0 + a;
        const float4 u4 = *reinterpret_cast<const float4*>(&s.uu[i][vv]);
        const float4 p0 = *reinterpret_cast<const float4*>(&s.red[0][th][a*4]);
        const float4 p1 = *reinterpret_cast<const float4*>(&s.red[1][th][a*4]);
        const float4 p2 = *reinterpret_cast<const float4*>(&s.red[2][th][a*4]);
        const float wi = s.w[i];
        float4 vq, wq;
        vq.x = u4.x + va[a][0] + p0.x + p1.x + p2.x;
        vq.y = u4.y + va[a][1] + p0.y + p1.y + p2.y;
        vq.z = u4.z + va[a][2] + p0.z + p1.z + p2.z;
        vq.w = u4.w + va[a][3] + p0.w + p1.w + p2.w;
        wq.x = vq.x*wi; wq.y = vq.y*wi; wq.z = vq.z*wi; wq.w = vq.w*wi;
        *reinterpret_cast<float4*>(&s.vn [i][vv]) = vq;
        *reinterpret_cast<float4*>(&s.vnw[i][vv]) = wq;
      }
    }
    __syncthreads();  // (4) vn ready; qg/uu free

    // ---- G1(n+1): qg + uu ----
    if (n + 1 < NCH) {
      const float* gq = g_qg + (rb + CC)*DK;
      #pragma unroll
      for (int rep = 0; rep < 4; rep++) {
        const int idx = t + rep*512;
        cpa16(&s.qg[swzo(idx >> 5, idx & 31)], gq + idx*4);
      }
      const int rr = t >> 3, c4 = (t & 7)*4;
      cpa16(&s.uu[rr][c4], g_u + (rb + CC + rr)*DK + v0 + c4);
    }
    cpa_commit();

    // ---- stage C: oa += attn @ vn over j4 = kh, kh+4, ... <= rg ----
    for (int j4 = kh; j4 <= rg; j4 += 4) {
      #pragma unroll
      for (int jj = 0; jj < 4; jj++) {
        const int j = j4*4 + jj;
        const float4 a4 = *reinterpret_cast<const float4*>(&s.atT[j][r0]);
        const float4 v4 = *reinterpret_cast<const float4*>(&s.vn[j][vv]);
        const float am[4] = {a4.x, a4.y, a4.z, a4.w};
        const float vm[4] = {v4.x, v4.y, v4.z, v4.w};
        #pragma unroll
        for (int a = 0; a < 4; a++)
          #pragma unroll
          for (int c = 0; c < 4; c++)
            oa[a][c] = fmaf(am[a], vm[c], oa[a][c]);
      }
    }
    if (kh) {
      #pragma unroll
      for (int a = 0; a < 4; a++)
        *reinterpret_cast<float4*>(&s.red[kh-1][th][a*4]) =
          make_float4(oa[a][0], oa[a][1], oa[a][2], oa[a][3]);
    }
    __syncthreads();  // (5) atT free

    // ---- G2(n+1): atT ----
    if (n + 1 < NCH) {
      const float* ga = g_at + (rb + CC)*CC;
      #pragma unroll
      for (int rep = 0; rep < 2; rep++) {
        const int idx = t + rep*512;
        cpa16(&s.atT[idx >> 4][(idx & 15)*4], ga + idx*4);
      }
    }
    cpa_commit();
    cpa_wait<2>();    // kn[n] landed (G1/G2 may pend)
    __syncthreads();  // (6)

    if (!kh) {
      #pragma unroll
      for (int a = 0; a < 4; a++) {
        const float4 p0 = *reinterpret_cast<const float4*>(&s.red[0][th][a*4]);
        const float4 p1 = *reinterpret_cast<const float4*>(&s.red[1][th][a*4]);
        const float4 p2 = *reinterpret_cast<const float4*>(&s.red[2][th][a*4]);
        float4 o4;
        o4.x = oa[a][0] + p0.x + p1.x + p2.x;
        o4.y = oa[a][1] + p0.y + p1.y + p2.y;
        o4.z = oa[a][2] + p0.z + p1.z + p2.z;
        o4.w = oa[a][3] + p0.w + p1.w + p2.w;
        *reinterpret_cast<float4*>(
            out + ((size_t)(b*Ssz + n*CC + r0 + a)*Hsz + h)*DK + v0 + vv) = o4;
      }
    }

    // ---- stage D: st = el*st + kn^T @ vnw (2 rows x 4 cols, all 512) ----
    {
      float acc[2][4] = {};
      #pragma unroll 4
      for (int i = 0; i < CC; i++) {
        const float2 k2 = *reinterpret_cast<const float2*>(&s.kn[i*DK + d0D]);
        const float4 v4 = *reinterpret_cast<const float4*>(&s.vnw[i][vvD]);
        const float vm[4] = {v4.x, v4.y, v4.z, v4.w};
        #pragma unroll
        for (int c = 0; c < 4; c++) {
          acc[0][c] = fmaf(k2.x, vm[c], acc[0][c]);
          acc[1][c] = fmaf(k2.y, vm[c], acc[1][c]);
        }
      }
      const float el = s.elv;
      #pragma unroll
      for (int a = 0; a < 2; a++) {
        float4 s4 = *reinterpret_cast<const float4*>(&s.st[d0D+a][vvD]);
        s4.x = fmaf(s4.x, el, acc[a][0]);
        s4.y = fmaf(s4.y, el, acc[a][1]);
        s4.z = fmaf(s4.z, el, acc[a][2]);
        s4.w = fmaf(s4.w, el, acc[a][3]);
        *reinterpret_cast<float4*>(&s.st[d0D+a][vvD]) = s4;
      }
    }
  }
}

// ================= launch =================
extern "C" void kernel_launch(void* const* d_in, const int* in_sizes, int n_in,
                              void* d_out, int out_size) {
  const float* q    = (const float*)d_in[0];
  const float* k    = (const float*)d_in[1];
  const float* v    = (const float*)d_in[2];
  const float* g    = (const float*)d_in[3];
  const float* beta = (const float*)d_in[4];
  float* out = (float*)d_out;

  cudaFuncSetAttribute((const void*)phase1_kernel,
                       cudaFuncAttributeMaxDynamicSharedMemorySize, (int)sizeof(P1S));
  cudaFuncSetAttribute((const void*)phase2_kernel,
                       cudaFuncAttributeMaxDynamicSharedMemorySize, (int)sizeof(P2S));

  phase1_kernel<<<BH*NCH, 256, sizeof(P1S)>>>(q, k, v, g, beta);
  phase2_kernel<<<BH*SPLIT, 512, sizeof(P2S)>>>(out);
}

// round 10
// speedup vs baseline: 1.6579x; 1.6579x over previous
#include <cuda_runtime.h>
#include <cuda_bf16.h>
#include <cstdint>

#define Bsz 2
#define Ssz 4096
#define Hsz 16
#define DK  128
#define CC  64
#define NCH (Ssz/CC)      // 64 chunks
#define BH  (Bsz*Hsz)     // 32
#define CCP 68            // phase1 transposed row pad
#define SPLIT 4
#define DVS (DK/SPLIT)    // 32
#define ATP 68            // phase2 attnT row pad
#define VNP 36            // phase2 DVS-wide row pad
#define REDW 20           // reduction row stride

// -------- scratch (device globals: allocation-free rule) --------
__device__ float g_qg[(size_t)BH*Ssz*DK];   // normalized q * Dk^-0.5 * exp(gcs)
__device__ float g_kn[(size_t)BH*Ssz*DK];   // normalized k
__device__ float g_u [(size_t)BH*Ssz*DK];   // Tinv @ (v*beta)
__device__ float g_w [(size_t)BH*Ssz*DK];   // Tinv @ (k*beta*exp(gcs))  (kcd)
__device__ float g_at[(size_t)BH*Ssz*CC];   // intra-chunk attn TRANSPOSED: [j][i]
__device__ float g_gc[(size_t)BH*Ssz];      // within-chunk cumsum of g

// 16B async copy global->shared
__device__ __forceinline__ void cpa16(void* dst, const void* src) {
  unsigned d = (unsigned)__cvta_generic_to_shared(dst);
  asm volatile("cp.async.cg.shared.global [%0], [%1], 16;" :: "r"(d), "l"(src));
}
__device__ __forceinline__ void cpa_commit() {
  asm volatile("cp.async.commit_group;");
}
template<int N> __device__ __forceinline__ void cpa_wait() {
  asm volatile("cp.async.wait_group %0;" :: "n"(N) : "memory");
}

// XOR bank swizzle for kc/qg tiles (row stride 128 floats; c4 in float4 units)
__device__ __forceinline__ int swz(int r, int c4) {
  return (r << 7) + ((c4 ^ ((r >> 2) & 3)) << 2);
}

struct P1S {
  float knT[DK][CCP];
  float qgT[DK][CCP];
  float A  [CC][CC];
  float gcs[CC];
  float bet[CC];
  float eg[CC];
  float er[CC];
  float ebg[CC];
};

struct P2S {
  float st [DK][VNP];      // state slice [DK][DVS]
  float kn [CC*DK];        // stride 128, unswizzled
  float kc [CC*DK];        // swizzled
  float qg [CC*DK];        // swizzled
  float uu [CC][VNP];
  float atT[CC][ATP];      // attn transposed [j][i]
  float vn [CC][VNP];
  float vnw[CC][VNP];      // vn * exp(g_last - gcs_i)
  float red[3][128][REDW]; // split-K partials (quarters 1..3)
  float w  [CC];
  float elv;               // exp(g_last)
};

// ================= Phase 1: per-chunk precompute (grid = BH*NCH) =================
__global__ void __launch_bounds__(256, 2) phase1_kernel(
    const float* __restrict__ q, const float* __restrict__ k,
    const float* __restrict__ v, const float* __restrict__ g,
    const float* __restrict__ beta)
{
  extern __shared__ char smraw[];
  P1S& s = *reinterpret_cast<P1S*>(smraw);
  const int t    = threadIdx.x;
  const int lane = t & 31;
  const int warp = t >> 5;
  const int cid = blockIdx.x;
  const int bh = cid / NCH, n = cid % NCH;
  const int b = bh / Hsz, h = bh % Hsz;
  const int s0 = n * CC;

  if (t < CC) {
    s.bet[t] = beta[(size_t)(b*Ssz + s0 + t)*Hsz + h];
    s.gcs[t] = g   [(size_t)(b*Ssz + s0 + t)*Hsz + h];
  }
  __syncthreads();
  if (t < CC) {
    float x = s.gcs[t];
    #pragma unroll
    for (int o = 1; o < 32; o <<= 1) {
      float y = __shfl_up_sync(0xffffffffu, x, o);
      if (lane >= o) x += y;
    }
    s.gcs[t] = x;
  }
  __syncthreads();
  if (t < CC) {
    float gi = s.gcs[t];
    if (t >= 32) { gi += s.gcs[31]; s.gcs[t] = gi; }
    const float e = __expf(gi);
    s.eg[t]  = e;
    s.er[t]  = __expf(-gi);
    s.ebg[t] = s.bet[t] * e;
    g_gc[(size_t)bh*Ssz + s0 + t] = gi;
  }
  __syncthreads();

  for (int r = warp; r < CC; r += 8) {
    const size_t base = ((size_t)(b*Ssz + s0 + r)*Hsz + h)*DK;
    float kv[4], qv[4];
    float ssk = 0.f, ssq = 0.f;
    #pragma unroll
    for (int i = 0; i < 4; i++) {
      kv[i] = k[base + lane + 32*i]; ssk = fmaf(kv[i], kv[i], ssk);
      qv[i] = q[base + lane + 32*i]; ssq = fmaf(qv[i], qv[i], ssq);
    }
    #pragma unroll
    for (int o = 16; o; o >>= 1) {
      ssk += __shfl_xor_sync(0xffffffffu, ssk, o);
      ssq += __shfl_xor_sync(0xffffffffu, ssq, o);
    }
    const float rk = rsqrtf(ssk + 1e-6f);
    const float rq = rsqrtf(ssq + 1e-6f) * 0.08838834764831845f * s.eg[r];
    const size_t ob = ((size_t)bh*Ssz + s0 + r)*DK;
    #pragma unroll
    for (int i = 0; i < 4; i++) {
      const int d = lane + 32*i;
      const float kk = kv[i]*rk, qq = qv[i]*rq;
      s.knT[d][r] = kk; g_kn[ob + d] = kk;
      s.qgT[d][r] = qq; g_qg[ob + d] = qq;
    }
  }
  __syncthreads();

  // ---- GEMM: A (strict lower) + attn (tril) stored TRANSPOSED ----
  {
    const int ti = t >> 4, tj = t & 15;
    const size_t atb = ((size_t)bh*Ssz + s0)*CC;
    if (tj <= ti) {
      float accA[4][4] = {}, accT[4][4] = {};
      #pragma unroll 4
      for (int d = 0; d < DK; d++) {
        const float4 kd4 = *reinterpret_cast<const float4*>(&s.knT[d][ti*4]);
        const float4 qd4 = *reinterpret_cast<const float4*>(&s.qgT[d][ti*4]);
        const float4 kj4 = *reinterpret_cast<const float4*>(&s.knT[d][tj*4]);
        const float kd[4] = {kd4.x, kd4.y, kd4.z, kd4.w};
        const float qd[4] = {qd4.x, qd4.y, qd4.z, qd4.w};
        const float kj[4] = {kj4.x, kj4.y, kj4.z, kj4.w};
        #pragma unroll
        for (int a = 0; a < 4; a++)
          #pragma unroll
          for (int c = 0; c < 4; c++) {
            accA[a][c] = fmaf(kd[a], kj[c], accA[a][c]);
            accT[a][c] = fmaf(qd[a], kj[c], accT[a][c]);
          }
      }
      const float erj[4] = {s.er[tj*4], s.er[tj*4+1], s.er[tj*4+2], s.er[tj*4+3]};
      #pragma unroll
      for (int a = 0; a < 4; a++) {
        const int i = ti*4 + a;
        const float bei = s.bet[i] * s.eg[i];
        float4 av; float* ap = &av.x;
        #pragma unroll
        for (int c = 0; c < 4; c++) {
          const int j = tj*4 + c;
          ap[c] = (j < i) ? accA[a][c]*bei*erj[c] : 0.f;
        }
        *reinterpret_cast<float4*>(&s.A[i][tj*4]) = av;
      }
      #pragma unroll
      for (int c = 0; c < 4; c++) {
        const int j = tj*4 + c;
        float4 tv; float* tp = &tv.x;
        #pragma unroll
        for (int a = 0; a < 4; a++) {
          const int i = ti*4 + a;
          tp[a] = (j <= i) ? accT[a][c]*erj[c] : 0.f;
        }
        *reinterpret_cast<float4*>(&g_at[atb + (size_t)j*CC + ti*4]) = tv;
      }
    } else {
      const float4 z = {0.f, 0.f, 0.f, 0.f};
      #pragma unroll
      for (int a = 0; a < 4; a++)
        *reinterpret_cast<float4*>(&s.A[ti*4 + a][tj*4]) = z;
      #pragma unroll
      for (int c = 0; c < 4; c++)
        *reinterpret_cast<float4*>(&g_at[atb + (size_t)(tj*4 + c)*CC + ti*4]) = z;
    }
  }
  __syncthreads();

  float xr[CC];
  if (t < DK) {
    #pragma unroll 8
    for (int i = 0; i < CC; i++)
      xr[i] = v[((size_t)(b*Ssz + s0 + i)*Hsz + h)*DK + t] * s.bet[i];
  } else {
    const int d = t - DK;
    #pragma unroll 8
    for (int i = 0; i < CC; i++)
      xr[i] = s.knT[d][i] * s.ebg[i];
  }

  #pragma unroll
  for (int i = 1; i < CC; i++) {
    const float4* Ai = reinterpret_cast<const float4*>(&s.A[i][0]);
    float a0 = 0.f, a1 = 0.f, a2 = 0.f, a3 = 0.f;
    const int nq = (i + 3) >> 2;
    #pragma unroll
    for (int j4 = 0; j4 < nq; j4++) {
      const float4 av = Ai[j4];
      a0 = fmaf(av.x, xr[j4*4+0], a0);
      a1 = fmaf(av.y, xr[j4*4+1], a1);
      a2 = fmaf(av.z, xr[j4*4+2], a2);
      a3 = fmaf(av.w, xr[j4*4+3], a3);
    }
    xr[i] -= (a0 + a1) + (a2 + a3);
  }

  {
    const size_t ob = ((size_t)bh*Ssz + s0)*DK;
    if (t < DK) {
      #pragma unroll 8
      for (int i = 0; i < CC; i++) g_u[ob + (size_t)i*DK + t] = xr[i];
    } else {
      const int d = t - DK;
      #pragma unroll 8
      for (int i = 0; i < CC; i++) g_w[ob + (size_t)i*DK + d] = xr[i];
    }
  }
}

// ===== Phase 2: scan (BH*SPLIT CTAs, 512 thr, 3-group rotating cp.async) =====
__global__ void __launch_bounds__(512, 1) phase2_kernel(float* __restrict__ out)
{
  extern __shared__ char smraw[];
  P2S& s = *reinterpret_cast<P2S*>(smraw);
  const int t  = threadIdx.x;
  const int bh = blockIdx.x / SPLIT;
  const int sp = blockIdx.x % SPLIT;
  const int b = bh / Hsz, h = bh % Hsz;
  const int v0 = sp * DVS;

  for (int i = t; i < DK*VNP; i += 512) (&s.st[0][0])[i] = 0.f;

  const int kh = t >> 7;        // d-quarter / split phase (0..3)
  const int th = t & 127;
  const int rg = th >> 3;       // 16 row groups (stages B/C)
  const int rgl = rg & 3;       // per-thread swizzle key
  const int r0 = rg * 4;
  const int vv = (th & 7) * 4;  // 4 cols
  const int d0D = (t >> 3) * 2; // stage D: 64 d-groups x 2 rows
  const int vvD = (t & 7) * 4;

  const size_t cb = (size_t)bh*Ssz;

  // ---- prologue: A(0) = {kc,qg,uu},  B(0) = {atT} ----
  {
    const float* gw = g_w  + cb*DK;
    const float* gq = g_qg + cb*DK;
    #pragma unroll
    for (int rep = 0; rep < 4; rep++) {
      const int idx = t + rep*512;
      const int so = swz(idx >> 5, idx & 31);
      cpa16(&s.kc[so], gw + idx*4);
      cpa16(&s.qg[so], gq + idx*4);
    }
    { const int rr = t >> 3, c4 = (t & 7)*4;
      cpa16(&s.uu[rr][c4], g_u + (cb + rr)*DK + v0 + c4); }
    cpa_commit();                                   // A(0)
    #pragma unroll
    for (int rep = 0; rep < 2; rep++) {
      const int idx = t + rep*512;
      cpa16(&s.atT[idx >> 4][(idx & 15)*4], g_at + cb*CC + idx*4);
    }
    cpa_commit();                                   // B(0)
  }

  for (int n = 0; n < NCH; n++) {
    const size_t rb = cb + n*CC;
    __syncthreads();  // (1) prev-chunk stage D done: kn buffer free

    // ---- C(n): kn(n) ----
    {
      const float* gk = g_kn + rb*DK;
      #pragma unroll
      for (int rep = 0; rep < 4; rep++) {
        const int idx = t + rep*512;
        cpa16(&s.kn[idx*4], gk + idx*4);
      }
      cpa_commit();
    }
    cpa_wait<2>();    // A(n) landed: kc/qg/uu
    __syncthreads();  // (2) publish
    if (t < CC) {
      const float gl = g_gc[rb + CC - 1];
      s.w[t] = __expf(gl - g_gc[rb + t]);
      if (t == CC-1) s.elv = __expf(gl);
    }

    // ---- stage B: va = -kc@st ; oa = qg@st  (quarter kh: 32 d's) ----
    float va[4][4] = {}, oa[4][4] = {};
    #pragma unroll 2
    for (int d4 = 0; d4 < 8; d4++) {
      const int c4b = kh*8 + d4;
      const int d = c4b*4;
      const int co = (c4b ^ rgl) << 2;   // swizzled column offset (floats)
      float stc[4][4];
      #pragma unroll
      for (int m = 0; m < 4; m++) {
        const float4 s4 = *reinterpret_cast<const float4*>(&s.st[d+m][vv]);
        stc[m][0]=s4.x; stc[m][1]=s4.y; stc[m][2]=s4.z; stc[m][3]=s4.w;
      }
      #pragma unroll
      for (int a = 0; a < 4; a++) {
        const int ofs = ((r0+a) << 7) + co;
        const float4 kc4 = *reinterpret_cast<const float4*>(&s.kc[ofs]);
        const float4 qg4 = *reinterpret_cast<const float4*>(&s.qg[ofs]);
        const float kcm[4] = {kc4.x, kc4.y, kc4.z, kc4.w};
        const float qgm[4] = {qg4.x, qg4.y, qg4.z, qg4.w};
        #pragma unroll
        for (int m = 0; m < 4; m++)
          #pragma unroll
          for (int c = 0; c < 4; c++) {
            va[a][c] = fmaf(-kcm[m], stc[m][c], va[a][c]);
            oa[a][c] = fmaf( qgm[m], stc[m][c], oa[a][c]);
          }
      }
    }
    if (kh) {
      #pragma unroll
      for (int a = 0; a < 4; a++)
        *reinterpret_cast<float4*>(&s.red[kh-1][th][a*4]) =
          make_float4(va[a][0], va[a][1], va[a][2], va[a][3]);
    }
    __syncthreads();  // (3)
    if (!kh) {
      #pragma unroll
      for (int a = 0; a < 4; a++) {
        const int i = r0 + a;
        const float4 u4 = *reinterpret_cast<const float4*>(&s.uu[i][vv]);
        const float4 p0 = *reinterpret_cast<const float4*>(&s.red[0][th][a*4]);
        const float4 p1 = *reinterpret_cast<const float4*>(&s.red[1][th][a*4]);
        const float4 p2 = *reinterpret_cast<const float4*>(&s.red[2][th][a*4]);
        const float wi = s.w[i];
        float4 vq, wq;
        vq.x = u4.x + va[a][0] + p0.x + p1.x + p2.x;
        vq.y = u4.y + va[a][1] + p0.y + p1.y + p2.y;
        vq.z = u4.z + va[a][2] + p0.z + p1.z + p2.z;
        vq.w = u4.w + va[a][3] + p0.w + p1.w + p2.w;
        wq.x = vq.x*wi; wq.y = vq.y*wi; wq.z = vq.z*wi; wq.w = vq.w*wi;
        *reinterpret_cast<float4*>(&s.vn [i][vv]) = vq;
        *reinterpret_cast<float4*>(&s.vnw[i][vv]) = wq;
      }
    }
    __syncthreads();  // (4) vn ready; kc/qg/uu dead

    // ---- A(n+1): kc,qg,uu ----
    if (n + 1 < NCH) {
      const float* gw = g_w  + (rb + CC)*DK;
      const float* gq = g_qg + (rb + CC)*DK;
      #pragma unroll
      for (int rep = 0; rep < 4; rep++) {
        const int idx = t + rep*512;
        const int so = swz(idx >> 5, idx & 31);
        cpa16(&s.kc[so], gw + idx*4);
        cpa16(&s.qg[so], gq + idx*4);
      }
      const int rr = t >> 3, c4 = (t & 7)*4;
      cpa16(&s.uu[rr][c4], g_u + (rb + CC + rr)*DK + v0 + c4);
    }
    cpa_commit();
    cpa_wait<2>();    // B(n) landed: atT
    __syncthreads();  // (4b) publish atT

    // ---- stage C: oa += attn @ vn over j4 = kh, kh+4, ... <= rg ----
    for (int j4 = kh; j4 <= rg; j4 += 4) {
      #pragma unroll
      for (int jj = 0; jj < 4; jj++) {
        const int j = j4*4 + jj;
        const float4 a4 = *reinterpret_cast<const float4*>(&s.atT[j][r0]);
        const float4 v4 = *reinterpret_cast<const float4*>(&s.vn[j][vv]);
        const float am[4] = {a4.x, a4.y, a4.z, a4.w};
        const float vm[4] = {v4.x, v4.y, v4.z, v4.w};
        #pragma unroll
        for (int a = 0; a < 4; a++)
          #pragma unroll
          for (int c = 0; c < 4; c++)
            oa[a][c] = fmaf(am[a], vm[c], oa[a][c]);
      }
    }
    if (kh) {
      #pragma unroll
      for (int a = 0; a < 4; a++)
        *reinterpret_cast<float4*>(&s.red[kh-1][th][a*4]) =
          make_float4(oa[a][0], oa[a][1], oa[a][2], oa[a][3]);
    }
    __syncthreads();  // (5) red-C ready; atT dead

    // ---- B(n+1): atT ----
    if (n + 1 < NCH) {
      const float* ga = g_at + (rb + CC)*CC;
      #pragma unroll
      for (int rep = 0; rep < 2; rep++) {
        const int idx = t + rep*512;
        cpa16(&s.atT[idx >> 4][(idx & 15)*4], ga + idx*4);
      }
    }
    cpa_commit();

    // output store overlaps the C(n) wait
    if (!kh) {
      #pragma unroll
      for (int a = 0; a < 4; a++) {
        const float4 p0 = *reinterpret_cast<const float4*>(&s.red[0][th][a*4]);
        const float4 p1 = *reinterpret_cast<const float4*>(&s.red[1][th][a*4]);
        const float4 p2 = *reinterpret_cast<const float4*>(&s.red[2][th][a*4]);
        float4 o4;
        o4.x = oa[a][0] + p0.x + p1.x + p2.x;
        o4.y = oa[a][1] + p0.y + p1.y + p2.y;
        o4.z = oa[a][2] + p0.z + p1.z + p2.z;
        o4.w = oa[a][3] + p0.w + p1.w + p2.w;
        *reinterpret_cast<float4*>(
            out + ((size_t)(b*Ssz + n*CC + r0 + a)*Hsz + h)*DK + v0 + vv) = o4;
      }
    }
    cpa_wait<2>();    // C(n) landed: kn
    __syncthreads();  // (5b) publish kn

    // ---- stage D: st = el*st + kn^T @ vnw (2 rows x 4 cols, all 512) ----
    {
      float acc[2][4] = {};
      #pragma unroll 4
      for (int i = 0; i < CC; i++) {
        const float2 k2 = *reinterpret_cast<const float2*>(&s.kn[i*DK + d0D]);
        const float4 v4 = *reinterpret_cast<const float4*>(&s.vnw[i][vvD]);
        const float vm[4] = {v4.x, v4.y, v4.z, v4.w};
        #pragma unroll
        for (int c = 0; c < 4; c++) {
          acc[0][c] = fmaf(k2.x, vm[c], acc[0][c]);
          acc[1][c] = fmaf(k2.y, vm[c], acc[1][c]);
        }
      }
      const float el = s.elv;
      #pragma unroll
      for (int a = 0; a < 2; a++) {
        float4 s4 = *reinterpret_cast<const float4*>(&s.st[d0D+a][vvD]);
        s4.x = fmaf(s4.x, el, acc[a][0]);
        s4.y = fmaf(s4.y, el, acc[a][1]);
        s4.z = fmaf(s4.z, el, acc[a][2]);
        s4.w = fmaf(s4.w, el, acc[a][3]);
        *reinterpret_cast<float4*>(&s.st[d0D+a][vvD]) = s4;
      }
    }
  }
}

// ================= launch =================
extern "C" void kernel_launch(void* const* d_in, const int* in_sizes, int n_in,
                              void* d_out, int out_size) {
  const float* q    = (const float*)d_in[0];
  const float* k    = (const float*)d_in[1];
  const float* v    = (const float*)d_in[2];
  const float* g    = (const float*)d_in[3];
  const float* beta = (const float*)d_in[4];
  float* out = (float*)d_out;

  cudaFuncSetAttribute((const void*)phase1_kernel,
                       cudaFuncAttributeMaxDynamicSharedMemorySize, (int)sizeof(P1S));
  cudaFuncSetAttribute((const void*)phase2_kernel,
                       cudaFuncAttributeMaxDynamicSharedMemorySize, (int)sizeof(P2S));

  phase1_kernel<<<BH*NCH, 256, sizeof(P1S)>>>(q, k, v, g, beta);
  phase2_kernel<<<BH*SPLIT, 512, sizeof(P2S)>>>(out);
}